// round 14
// baseline (speedup 1.0000x reference)
#include <cuda_runtime.h>
#include <cstdint>

// 12-bit ripple-carry adder over {0,1}-valued float32 arrays.
// A,B: [BATCH, 12] float32, col 11 = LSB (weight 2^(11-i)).
// Out: sums [BATCH,12] at d_out[0..B*12), carry [BATCH] at d_out[B*12..B*13).
//
// FINAL (converged, best-measured configuration: ~84us kernel, ~6.82 TB/s =
// 85% of HBM spec, traffic at the 620MB floor). 256-bit streaming
// (sm_100a ld/st.global.v8.f32): thread t owns the 32B chunk pair {2t,2t+1}.
// Per thread: 2x v8 evict-first loads, nibble pack to smem, __syncthreads,
// carry store (hoisted to overlap scatter compute), row assembly (12-bit
// integer add), 1x v8 evict-first store. TPB=384 -> 768 chunks = 256 rows
// per block, one-shot grid of 16384 blocks.

__device__ __forceinline__ unsigned f2b(float x) {
    return __float_as_uint(x) != 0u ? 1u : 0u;   // x is exactly 0.0f or 1.0f
}

struct f8 { float v[8]; };

__device__ __forceinline__ f8 ldg256_cs(const float* p) {
    f8 r;
    asm volatile("ld.global.cs.v8.f32 {%0,%1,%2,%3,%4,%5,%6,%7}, [%8];"
                 : "=f"(r.v[0]), "=f"(r.v[1]), "=f"(r.v[2]), "=f"(r.v[3]),
                   "=f"(r.v[4]), "=f"(r.v[5]), "=f"(r.v[6]), "=f"(r.v[7])
                 : "l"(p));
    return r;
}

__device__ __forceinline__ void stg256_cs(float* p, const f8& r) {
    asm volatile("st.global.cs.v8.f32 [%0], {%1,%2,%3,%4,%5,%6,%7,%8};"
                 :: "l"(p),
                    "f"(r.v[0]), "f"(r.v[1]), "f"(r.v[2]), "f"(r.v[3]),
                    "f"(r.v[4]), "f"(r.v[5]), "f"(r.v[6]), "f"(r.v[7])
                 : "memory");
}

__device__ __forceinline__ unsigned pack4(const float* p) {
    return (f2b(p[0]) << 3) | (f2b(p[1]) << 2) | (f2b(p[2]) << 1) | f2b(p[3]);
}

__device__ __forceinline__ unsigned row_sum(const unsigned* nib, int rb) {
    unsigned c0 = nib[rb + 0], c1 = nib[rb + 1], c2 = nib[rb + 2];
    // chunk j of a row holds bit-weights: j=0 -> 11..8, j=1 -> 7..4, j=2 -> 3..0
    unsigned av = ((c0 & 0xFu) << 8) | ((c1 & 0xFu) << 4) | (c2 & 0xFu);
    unsigned bv = ((c0 >> 4) << 8)  | (((c1 >> 4) & 0xFu) << 4) | ((c2 >> 4) & 0xFu);
    return av + bv;   // 13-bit result
}

__device__ __forceinline__ void nib_to_4f(unsigned on, float* o) {
    o[0] = (on & 8u) ? 1.0f : 0.0f;
    o[1] = (on & 4u) ? 1.0f : 0.0f;
    o[2] = (on & 2u) ? 1.0f : 0.0f;
    o[3] = (on & 1u) ? 1.0f : 0.0f;
}

#define TPB 384
#define CHUNKS_PER_BLOCK (TPB * 2)             // 768
#define ROWS_PER_BLOCK (CHUNKS_PER_BLOCK / 3)  // 256

// ---- Fast path: nchunks % CHUNKS_PER_BLOCK == 0, no bounds checks ----
__global__ void __launch_bounds__(TPB) adder12_exact(
    const float* __restrict__ A,
    const float* __restrict__ B,
    float* __restrict__ S,
    float* __restrict__ carry)
{
    __shared__ unsigned nib[CHUNKS_PER_BLOCK];

    const int tid = threadIdx.x;
    const int c0 = blockIdx.x * CHUNKS_PER_BLOCK + 2 * tid;  // even chunk
    const long f0 = (long)c0 * 4;                            // float offset

    // Two 256-bit evict-first loads (each covers chunks c0, c0+1).
    f8 a = ldg256_cs(A + f0);
    f8 b = ldg256_cs(B + f0);

    nib[2 * tid]     = pack4(a.v)     | (pack4(b.v)     << 4);
    nib[2 * tid + 1] = pack4(a.v + 4) | (pack4(b.v + 4) << 4);
    __syncthreads();

    // Carry-out first: its STG enters the LSU while the scatter nibbles are
    // still being computed. Threads 0..255 cover the block's 256 rows.
    if (tid < ROWS_PER_BLOCK) {
        unsigned s = row_sum(nib, tid * 3);
        __stcs(&carry[blockIdx.x * ROWS_PER_BLOCK + tid],
               (s >> 12) ? 1.0f : 0.0f);
    }

    // Sums for the two owned chunks (adjacent; rows may differ).
    f8 o;
    {
        int k = 2 * tid;
        int r0 = k / 3, p0 = k - r0 * 3;
        unsigned s0 = row_sum(nib, r0 * 3);
        nib_to_4f((s0 >> (8 - 4 * p0)) & 0xFu, o.v);
        int k1 = k + 1;
        int r1 = k1 / 3, p1 = k1 - r1 * 3;
        unsigned s1 = (r1 == r0) ? s0 : row_sum(nib, r1 * 3);
        nib_to_4f((s1 >> (8 - 4 * p1)) & 0xFu, o.v + 4);
    }
    stg256_cs(S + f0, o);
}

// ---- Guarded fallback (float4 path) for non-divisible sizes ----
__global__ void __launch_bounds__(TPB) adder12_guarded(
    const float4* __restrict__ A4,
    const float4* __restrict__ B4,
    float4* __restrict__ S4,
    float* __restrict__ carry,
    int nchunks, int batch)
{
    __shared__ unsigned nib[CHUNKS_PER_BLOCK];

    const int tid = threadIdx.x;
    const int base = blockIdx.x * CHUNKS_PER_BLOCK + tid;
    const bool v0 = (base < nchunks);
    const bool v1 = (base + TPB < nchunks);

    float4 a0, b0, a1, b1;
    if (v0) { a0 = __ldcs(&A4[base]); b0 = __ldcs(&B4[base]); }
    if (v1) { a1 = __ldcs(&A4[base + TPB]); b1 = __ldcs(&B4[base + TPB]); }

    nib[tid] = v0 ? ((pack4(&a0.x)) | (pack4(&b0.x) << 4)) : 0u;
    nib[tid + TPB] = v1 ? ((pack4(&a1.x)) | (pack4(&b1.x) << 4)) : 0u;
    __syncthreads();

#pragma unroll
    for (int k = 0; k < 2; k++) {
        int li = tid + k * TPB;
        int lrow = li / 3;
        int part = li - lrow * 3;
        unsigned s = row_sum(nib, lrow * 3);
        unsigned on = (s >> (8 - 4 * part)) & 0xFu;
        float4 o;
        nib_to_4f(on, &o.x);
        if (k == 0 ? v0 : v1) __stcs(&S4[base + k * TPB], o);
    }

    if (tid < ROWS_PER_BLOCK) {
        int row = blockIdx.x * ROWS_PER_BLOCK + tid;
        if (row < batch) {
            unsigned s = row_sum(nib, tid * 3);
            __stcs(&carry[row], (s >> 12) ? 1.0f : 0.0f);
        }
    }
}

extern "C" void kernel_launch(void* const* d_in, const int* in_sizes, int n_in,
                              void* d_out, int out_size) {
    const float* A = (const float*)d_in[0];
    const float* B = (const float*)d_in[1];
    float* out = (float*)d_out;

    int batch = in_sizes[0] / 12;
    int nchunks = batch * 3;

    float* sums = out;
    float* carry = out + (long)batch * 12;

    if (nchunks % CHUNKS_PER_BLOCK == 0) {
        int blocks = nchunks / CHUNKS_PER_BLOCK;
        adder12_exact<<<blocks, TPB>>>(A, B, sums, carry);
    } else {
        int blocks = (nchunks + CHUNKS_PER_BLOCK - 1) / CHUNKS_PER_BLOCK;
        adder12_guarded<<<blocks, TPB>>>(
            (const float4*)A, (const float4*)B, (float4*)sums, carry,
            nchunks, batch);
    }
}

// round 15
// speedup vs baseline: 1.0003x; 1.0003x over previous
#include <cuda_runtime.h>
#include <cstdint>

// 12-bit ripple-carry adder over {0,1}-valued float32 arrays.
// A,B: [BATCH, 12] float32, col 11 = LSB (weight 2^(11-i)).
// Out: sums [BATCH,12] at d_out[0..B*12), carry [BATCH] at d_out[B*12..B*13).
//
// FINAL — converged best-measured configuration (84.0-84.2us kernel, ~6.82
// TB/s = 85% of HBM spec, traffic at the 620MB information-theoretic floor;
// 14 rounds of structural search all land within +-2% of this point).
// 256-bit streaming (sm_100a ld/st.global.v8.f32): thread t owns the 32B
// chunk pair {2t, 2t+1}. Per thread: 2x v8 evict-first loads, nibble pack to
// smem, __syncthreads, row assembly (12-bit integer add), 1x v8 evict-first
// store, then coalesced scalar carry store. TPB=384 -> 768 chunks = 256 rows
// per block, one-shot grid of 16384 blocks.

__device__ __forceinline__ unsigned f2b(float x) {
    return __float_as_uint(x) != 0u ? 1u : 0u;   // x is exactly 0.0f or 1.0f
}

struct f8 { float v[8]; };

__device__ __forceinline__ f8 ldg256_cs(const float* p) {
    f8 r;
    asm volatile("ld.global.cs.v8.f32 {%0,%1,%2,%3,%4,%5,%6,%7}, [%8];"
                 : "=f"(r.v[0]), "=f"(r.v[1]), "=f"(r.v[2]), "=f"(r.v[3]),
                   "=f"(r.v[4]), "=f"(r.v[5]), "=f"(r.v[6]), "=f"(r.v[7])
                 : "l"(p));
    return r;
}

__device__ __forceinline__ void stg256_cs(float* p, const f8& r) {
    asm volatile("st.global.cs.v8.f32 [%0], {%1,%2,%3,%4,%5,%6,%7,%8};"
                 :: "l"(p),
                    "f"(r.v[0]), "f"(r.v[1]), "f"(r.v[2]), "f"(r.v[3]),
                    "f"(r.v[4]), "f"(r.v[5]), "f"(r.v[6]), "f"(r.v[7])
                 : "memory");
}

__device__ __forceinline__ unsigned pack4(const float* p) {
    return (f2b(p[0]) << 3) | (f2b(p[1]) << 2) | (f2b(p[2]) << 1) | f2b(p[3]);
}

__device__ __forceinline__ unsigned row_sum(const unsigned* nib, int rb) {
    unsigned c0 = nib[rb + 0], c1 = nib[rb + 1], c2 = nib[rb + 2];
    // chunk j of a row holds bit-weights: j=0 -> 11..8, j=1 -> 7..4, j=2 -> 3..0
    unsigned av = ((c0 & 0xFu) << 8) | ((c1 & 0xFu) << 4) | (c2 & 0xFu);
    unsigned bv = ((c0 >> 4) << 8)  | (((c1 >> 4) & 0xFu) << 4) | ((c2 >> 4) & 0xFu);
    return av + bv;   // 13-bit result
}

__device__ __forceinline__ void nib_to_4f(unsigned on, float* o) {
    o[0] = (on & 8u) ? 1.0f : 0.0f;
    o[1] = (on & 4u) ? 1.0f : 0.0f;
    o[2] = (on & 2u) ? 1.0f : 0.0f;
    o[3] = (on & 1u) ? 1.0f : 0.0f;
}

#define TPB 384
#define CHUNKS_PER_BLOCK (TPB * 2)             // 768
#define ROWS_PER_BLOCK (CHUNKS_PER_BLOCK / 3)  // 256

// ---- Fast path: nchunks % CHUNKS_PER_BLOCK == 0, no bounds checks ----
__global__ void __launch_bounds__(TPB) adder12_exact(
    const float* __restrict__ A,
    const float* __restrict__ B,
    float* __restrict__ S,
    float* __restrict__ carry)
{
    __shared__ unsigned nib[CHUNKS_PER_BLOCK];

    const int tid = threadIdx.x;
    const int c0 = blockIdx.x * CHUNKS_PER_BLOCK + 2 * tid;  // even chunk
    const long f0 = (long)c0 * 4;                            // float offset

    // Two 256-bit evict-first loads (each covers chunks c0, c0+1).
    f8 a = ldg256_cs(A + f0);
    f8 b = ldg256_cs(B + f0);

    nib[2 * tid]     = pack4(a.v)     | (pack4(b.v)     << 4);
    nib[2 * tid + 1] = pack4(a.v + 4) | (pack4(b.v + 4) << 4);
    __syncthreads();

    // Sums for the two owned chunks (adjacent; rows may differ).
    f8 o;
    {
        int k = 2 * tid;
        int r0 = k / 3, p0 = k - r0 * 3;
        unsigned s0 = row_sum(nib, r0 * 3);
        nib_to_4f((s0 >> (8 - 4 * p0)) & 0xFu, o.v);
        int k1 = k + 1;
        int r1 = k1 / 3, p1 = k1 - r1 * 3;
        unsigned s1 = (r1 == r0) ? s0 : row_sum(nib, r1 * 3);
        nib_to_4f((s1 >> (8 - 4 * p1)) & 0xFu, o.v + 4);
    }
    stg256_cs(S + f0, o);

    // Carry-out: threads 0..255 handle the block's 256 rows (coalesced 1KB).
    if (tid < ROWS_PER_BLOCK) {
        unsigned s = row_sum(nib, tid * 3);
        __stcs(&carry[blockIdx.x * ROWS_PER_BLOCK + tid],
               (s >> 12) ? 1.0f : 0.0f);
    }
}

// ---- Guarded fallback (float4 path) for non-divisible sizes ----
__global__ void __launch_bounds__(TPB) adder12_guarded(
    const float4* __restrict__ A4,
    const float4* __restrict__ B4,
    float4* __restrict__ S4,
    float* __restrict__ carry,
    int nchunks, int batch)
{
    __shared__ unsigned nib[CHUNKS_PER_BLOCK];

    const int tid = threadIdx.x;
    const int base = blockIdx.x * CHUNKS_PER_BLOCK + tid;
    const bool v0 = (base < nchunks);
    const bool v1 = (base + TPB < nchunks);

    float4 a0, b0, a1, b1;
    if (v0) { a0 = __ldcs(&A4[base]); b0 = __ldcs(&B4[base]); }
    if (v1) { a1 = __ldcs(&A4[base + TPB]); b1 = __ldcs(&B4[base + TPB]); }

    nib[tid] = v0 ? ((pack4(&a0.x)) | (pack4(&b0.x) << 4)) : 0u;
    nib[tid + TPB] = v1 ? ((pack4(&a1.x)) | (pack4(&b1.x) << 4)) : 0u;
    __syncthreads();

#pragma unroll
    for (int k = 0; k < 2; k++) {
        int li = tid + k * TPB;
        int lrow = li / 3;
        int part = li - lrow * 3;
        unsigned s = row_sum(nib, lrow * 3);
        unsigned on = (s >> (8 - 4 * part)) & 0xFu;
        float4 o;
        nib_to_4f(on, &o.x);
        if (k == 0 ? v0 : v1) __stcs(&S4[base + k * TPB], o);
    }

    if (tid < ROWS_PER_BLOCK) {
        int row = blockIdx.x * ROWS_PER_BLOCK + tid;
        if (row < batch) {
            unsigned s = row_sum(nib, tid * 3);
            __stcs(&carry[row], (s >> 12) ? 1.0f : 0.0f);
        }
    }
}

extern "C" void kernel_launch(void* const* d_in, const int* in_sizes, int n_in,
                              void* d_out, int out_size) {
    const float* A = (const float*)d_in[0];
    const float* B = (const float*)d_in[1];
    float* out = (float*)d_out;

    int batch = in_sizes[0] / 12;
    int nchunks = batch * 3;

    float* sums = out;
    float* carry = out + (long)batch * 12;

    if (nchunks % CHUNKS_PER_BLOCK == 0) {
        int blocks = nchunks / CHUNKS_PER_BLOCK;
        adder12_exact<<<blocks, TPB>>>(A, B, sums, carry);
    } else {
        int blocks = (nchunks + CHUNKS_PER_BLOCK - 1) / CHUNKS_PER_BLOCK;
        adder12_guarded<<<blocks, TPB>>>(
            (const float4*)A, (const float4*)B, (float4*)sums, carry,
            nchunks, batch);
    }
}